// round 17
// baseline (speedup 1.0000x reference)
#include <cuda_runtime.h>
#include <math.h>

// Problem constants (fixed by setup_inputs)
#define NB 16
#define NP 32768
#define NG 128
#define TK 4                      // top-k (expand_num)
#define TG 2                      // truths per block
#define NSTRM 4                   // streams (warps) per truth
#define WPB (TG * NSTRM)          // 8 warps
#define NT1 (WPB * 32)            // 256 threads
#define TILE 2048                 // smem tile of priors
#define NTILES (NP / TILE)        // 16 tiles (whole image per block)
#define ROWS (TILE / NSTRM)       // 512 priors per stream per tile
#define SITER (ROWS / 32)         // 16 warp-iters per stream per tile
#define NBG (NB * NG)             // 2048 truths

// ── (q, idx) total order: value desc, index asc (jax.lax.top_k stable) ──────
__device__ __forceinline__ bool better(float av, int ai, float bv, int bi) {
    return (av > bv) || (av == bv && ai < bi);
}

// ── Single kernel: block = (image, 2 truths); all-reduction block-local ─────
__global__ __launch_bounds__(NT1)
void ptl_kernel(const float* __restrict__ rois,
                const float* __restrict__ targets,
                float* __restrict__ out) {
    const int blk  = blockIdx.x;                   // NB * NG/TG = 1024
    const int b    = blk / (NG / TG);
    const int tgrp = blk % (NG / TG);
    const int tid  = threadIdx.x;
    const int lane = tid & 31;
    const int w    = tid >> 5;
    const int t    = w >> 2;                       // warp's truth (0..1)
    const int s    = w & 3;                        // warp's stream (0..3)
    const int g    = tgrp * TG + t;                // global truth in image

    __shared__ float4 s_pri[TILE];                 // 32 KB
    __shared__ float2 s_cand[WPB][TK];             // per-(truth,stream) top-4

    // My warp's truth box (uniform across lanes; L1-broadcast).
    float4 tb = __ldg(&((const float4*)targets)[(size_t)b * NG + g]);
    const float tx1 = tb.x, ty1 = tb.y, tx2 = tb.z, ty2 = tb.w;
    const float tar = __fmul_rn(tx2 - tx1, ty2 - ty1);    // rounded once (jax)

    // Warp-replicated top-4 as (inter, denom, idx); sentinel ratio = -1/1.
    float Li0 = -1.0f, Li1 = -1.0f, Li2 = -1.0f, Li3 = -1.0f;
    float Ld0 =  1.0f, Ld1 =  1.0f, Ld2 =  1.0f, Ld3 =  1.0f;
    int   Lx0 = 0x7fffffff, Lx1 = 0x7fffffff, Lx2 = 0x7fffffff, Lx3 = 0x7fffffff;

    const float4* pri = (const float4*)(rois + ((size_t)b * 2 + 1) * (size_t)NP * 4);

    for (int tile = 0; tile < NTILES; tile++) {
        const int base = tile * TILE;

        // Cooperative stage: 256 threads x 8 float4 each.
#pragma unroll
        for (int k = tid; k < TILE; k += NT1)
            s_pri[k] = __ldg(&pri[base + k]);
        __syncthreads();

        // My stream's rows of this tile: ascending global index order.
        const int sbase = base + s * ROWS;
#pragma unroll 4
        for (int i = 0; i < SITER; i++) {
            float4 pr = s_pri[s * ROWS + i * 32 + lane]; // LDS.128, conflict-free
            float area_p = __fmul_rn(pr.z - pr.x, pr.w - pr.y);  // regs, jax bits
            float lx = fmaxf(tx1, pr.x);
            float ly = fmaxf(ty1, pr.y);
            float rx = fminf(tx2, pr.z);
            float ry = fminf(ty2, pr.w);
            float wd = fmaxf(rx - lx, 0.0f);
            float ht = fmaxf(ry - ly, 0.0f);
            float inter = __fmul_rn(wd, ht);
            float denom = (tar + area_p) - inter;

            // Exact cross-mult gate vs warp's current 4th (strict >).
            bool pass = __fmul_rn(inter, Ld3) > __fmul_rn(Li3, denom);
            unsigned m = __ballot_sync(0xffffffffu, pass);
            while (m) {                          // uniform loop (rare)
                int l = __ffs(m) - 1; m &= m - 1;
                float ci = __shfl_sync(0xffffffffu, inter, l);
                float cd = __shfl_sync(0xffffffffu, denom, l);
                int   cx = sbase + i * 32 + l;   // global prior index (uniform)
                // Exact re-check vs (possibly updated) list.
                bool c3 = __fmul_rn(ci, Ld3) > __fmul_rn(Li3, cd);
                if (c3) {
                    bool c2 = __fmul_rn(ci, Ld2) > __fmul_rn(Li2, cd);
                    bool c1 = __fmul_rn(ci, Ld1) > __fmul_rn(Li1, cd);
                    bool c0 = __fmul_rn(ci, Ld0) > __fmul_rn(Li0, cd);
                    Li3 = c2 ? Li2 : ci;  Ld3 = c2 ? Ld2 : cd;  Lx3 = c2 ? Lx2 : cx;
                    Li2 = c1 ? Li1 : (c2 ? ci : Li2);
                    Ld2 = c1 ? Ld1 : (c2 ? cd : Ld2);
                    Lx2 = c1 ? Lx1 : (c2 ? cx : Lx2);
                    Li1 = c0 ? Li0 : (c1 ? ci : Li1);
                    Ld1 = c0 ? Ld0 : (c1 ? cd : Ld1);
                    Lx1 = c0 ? Lx0 : (c1 ? cx : Lx1);
                    Li0 = c0 ? ci : Li0;
                    Ld0 = c0 ? cd : Ld0;
                    Lx0 = c0 ? cx : Lx0;
                }
            }
        }
        __syncthreads();
    }

    // Finalize: lanes 0..3 compute exact jax-bit IoU, write to shared.
    if (lane < TK) {
        float si = (lane == 0) ? Li0 : (lane == 1) ? Li1 : (lane == 2) ? Li2 : Li3;
        float sd = (lane == 0) ? Ld0 : (lane == 1) ? Ld1 : (lane == 2) ? Ld2 : Ld3;
        int   sx = (lane == 0) ? Lx0 : (lane == 1) ? Lx1 : (lane == 2) ? Lx2 : Lx3;
        float q = (sx == 0x7fffffff) ? -1e30f : __fdiv_rn(si, sd);
        s_cand[w][lane] = make_float2(q, __int_as_float(sx));
    }
    __syncthreads();

    // Block-local merge + encode: 8 threads, one per (truth, k).
    if (tid < TG * TK) {
        const int mt = tid >> 2;                   // truth within block (0..1)
        const int k  = tid & 3;
        const int bg = b * NG + tgrp * TG + mt;

        float v[TK]; int ix[TK];
#pragma unroll
        for (int j = 0; j < TK; j++) { v[j] = -1e30f; ix[j] = 0x7fffffff; }

        // 16 candidates: 4 streams x 4; any order valid (full (q,idx) compare).
#pragma unroll
        for (int ss = 0; ss < NSTRM; ss++) {
#pragma unroll
            for (int j = 0; j < TK; j++) {
                float2 cc = s_cand[mt * NSTRM + ss][j];
                float q = cc.x; int qi = __float_as_int(cc.y);
                if (better(q, qi, v[3], ix[3])) {
                    if (better(q, qi, v[2], ix[2])) {
                        v[3] = v[2]; ix[3] = ix[2];
                        if (better(q, qi, v[1], ix[1])) {
                            v[2] = v[1]; ix[2] = ix[1];
                            if (better(q, qi, v[0], ix[0])) {
                                v[1] = v[0]; ix[1] = ix[0];
                                v[0] = q; ix[0] = qi;
                            } else { v[1] = q; ix[1] = qi; }
                        } else { v[2] = q; ix[2] = qi; }
                    } else { v[3] = q; ix[3] = qi; }
                }
            }
        }
        const int p = ix[k];

        // Encode one output row (identical rounding to reference).
        float gx1 = targets[(size_t)bg * 4 + 0];
        float gy1 = targets[(size_t)bg * 4 + 1];
        float gx2 = targets[(size_t)bg * 4 + 2];
        float gy2 = targets[(size_t)bg * 4 + 3];
        float gcx = (gx1 + gx2) * 0.5f;
        float gcy = (gy1 + gy2) * 0.5f;
        float gw  = gx2 - gx1;
        float gh  = gy2 - gy1;

        float4 pr = __ldg(&pri[p]);
        float pcx = (pr.x + pr.z) * 0.5f;
        float pcy = (pr.y + pr.w) * 0.5f;
        float pw  = pr.z - pr.x;
        float ph  = pr.w - pr.y;
        float4 o;
        o.x = (gcx - pcx) / (0.1f * pw);
        o.y = (gcy - pcy) / (0.1f * ph);
        o.z = logf(gw / pw) / 0.2f;
        o.w = logf(gh / ph) / 0.2f;
        ((float4*)out)[(size_t)bg * TK + k] = o;
    }
}

extern "C" void kernel_launch(void* const* d_in, const int* in_sizes, int n_in,
                              void* d_out, int out_size) {
    const float* rois    = (const float*)d_in[0];   // (16, 2, 32768, 4) f32
    const float* targets = (const float*)d_in[1];   // (16, 128, 4) f32
    float* out           = (float*)d_out;           // (16, 512, 4) f32
    (void)in_sizes; (void)n_in; (void)out_size;

    ptl_kernel<<<NB * (NG / TG), NT1>>>(rois, targets, out);
}